// round 2
// baseline (speedup 1.0000x reference)
#include <cuda_runtime.h>
#include <math.h>

// Problem constants
#define BATCH 4
#define SEQ   2048
#define HID   1024

// Tiling
#define BM 128
#define BN 128
#define BK 8
#define TM 8
#define TN 8
#define NTHREADS 256

// Scratch (allocation-free rule: __device__ globals)
__device__ float g_q[(size_t)BATCH * SEQ * HID];
__device__ float g_k[(size_t)BATCH * SEQ * HID];
__device__ float g_v[(size_t)BATCH * SEQ * HID];
__device__ float g_s[(size_t)BATCH * SEQ * SEQ];

// ---------------------------------------------------------------------------
// C[m,n] = alpha * sum_k A[m,k] * B[n,k]  (+ bias[n])
// A: [M,K] row-major.  B: [N,K] row-major (i.e. "NT" gemm — inner dim contiguous
// for both). Used for QKV projections (B = W[e,d]) and for scores (B = K[s,d]).
// Requires M%128==0, N%128==0, K%8==0 (true for all our shapes).
// ---------------------------------------------------------------------------
__global__ __launch_bounds__(NTHREADS)
void gemm_nt(const float* __restrict__ A, const float* __restrict__ B,
             const float* __restrict__ bias, float* __restrict__ C,
             int M, int N, int K, float alpha,
             long long strideA, long long strideB, long long strideC)
{
    __shared__ float As[BK][BM];
    __shared__ float Bs[BK][BN];

    const float* Ab = A + (long long)blockIdx.z * strideA;
    const float* Bb = B + (long long)blockIdx.z * strideB;
    float*       Cb = C + (long long)blockIdx.z * strideC;

    const int m0 = blockIdx.y * BM;
    const int n0 = blockIdx.x * BN;
    const int tid = threadIdx.x;
    const int tr = tid >> 4;    // 0..15 -> row group
    const int tc = tid & 15;    // 0..15 -> col group

    // Load mapping: 128 rows x 8 k, one float4 per thread along K
    const int l_row = tid >> 1;          // 0..127
    const int l_col = (tid & 1) * 4;     // 0 or 4

    float acc[TM][TN];
    #pragma unroll
    for (int i = 0; i < TM; i++)
        #pragma unroll
        for (int j = 0; j < TN; j++) acc[i][j] = 0.0f;

    for (int k0 = 0; k0 < K; k0 += BK) {
        float4 a4 = *reinterpret_cast<const float4*>(
            &Ab[(long long)(m0 + l_row) * K + k0 + l_col]);
        float4 b4 = *reinterpret_cast<const float4*>(
            &Bb[(long long)(n0 + l_row) * K + k0 + l_col]);
        As[l_col + 0][l_row] = a4.x;
        As[l_col + 1][l_row] = a4.y;
        As[l_col + 2][l_row] = a4.z;
        As[l_col + 3][l_row] = a4.w;
        Bs[l_col + 0][l_row] = b4.x;
        Bs[l_col + 1][l_row] = b4.y;
        Bs[l_col + 2][l_row] = b4.z;
        Bs[l_col + 3][l_row] = b4.w;
        __syncthreads();

        #pragma unroll
        for (int k = 0; k < BK; k++) {
            float a[TM], b[TN];
            #pragma unroll
            for (int i = 0; i < TM; i++) a[i] = As[k][tr * TM + i];
            #pragma unroll
            for (int j = 0; j < TN; j++) b[j] = Bs[k][tc * TN + j];
            #pragma unroll
            for (int i = 0; i < TM; i++)
                #pragma unroll
                for (int j = 0; j < TN; j++)
                    acc[i][j] = fmaf(a[i], b[j], acc[i][j]);
        }
        __syncthreads();
    }

    #pragma unroll
    for (int i = 0; i < TM; i++) {
        const long long crow = (long long)(m0 + tr * TM + i) * N;
        #pragma unroll
        for (int j = 0; j < TN; j++) {
            const int n = n0 + tc * TN + j;
            float v = alpha * acc[i][j];
            if (bias) v += bias[n];
            Cb[crow + n] = v;
        }
    }
}

// ---------------------------------------------------------------------------
// C[m,n] = sum_k A[m,k] * B[k,n]   ("NN" gemm). Used for attn @ V.
// A: [M,K] row-major, B: [K,N] row-major.
// ---------------------------------------------------------------------------
__global__ __launch_bounds__(NTHREADS)
void gemm_nn(const float* __restrict__ A, const float* __restrict__ B,
             float* __restrict__ C,
             int M, int N, int K,
             long long strideA, long long strideB, long long strideC)
{
    __shared__ float As[BK][BM];
    __shared__ float Bs[BK][BN];

    const float* Ab = A + (long long)blockIdx.z * strideA;
    const float* Bb = B + (long long)blockIdx.z * strideB;
    float*       Cb = C + (long long)blockIdx.z * strideC;

    const int m0 = blockIdx.y * BM;
    const int n0 = blockIdx.x * BN;
    const int tid = threadIdx.x;
    const int tr = tid >> 4;
    const int tc = tid & 15;

    // A load: 128 rows x 8 k (transpose into As)
    const int la_row = tid >> 1;
    const int la_col = (tid & 1) * 4;
    // B load: 8 k-rows x 128 n, contiguous in n
    const int lb_row = tid >> 5;          // 0..7
    const int lb_col = (tid & 31) * 4;    // 0..124

    float acc[TM][TN];
    #pragma unroll
    for (int i = 0; i < TM; i++)
        #pragma unroll
        for (int j = 0; j < TN; j++) acc[i][j] = 0.0f;

    for (int k0 = 0; k0 < K; k0 += BK) {
        float4 a4 = *reinterpret_cast<const float4*>(
            &Ab[(long long)(m0 + la_row) * K + k0 + la_col]);
        float4 b4 = *reinterpret_cast<const float4*>(
            &Bb[(long long)(k0 + lb_row) * N + n0 + lb_col]);
        As[la_col + 0][la_row] = a4.x;
        As[la_col + 1][la_row] = a4.y;
        As[la_col + 2][la_row] = a4.z;
        As[la_col + 3][la_row] = a4.w;
        *reinterpret_cast<float4*>(&Bs[lb_row][lb_col]) = b4;
        __syncthreads();

        #pragma unroll
        for (int k = 0; k < BK; k++) {
            float a[TM], b[TN];
            #pragma unroll
            for (int i = 0; i < TM; i++) a[i] = As[k][tr * TM + i];
            #pragma unroll
            for (int j = 0; j < TN; j++) b[j] = Bs[k][tc * TN + j];
            #pragma unroll
            for (int i = 0; i < TM; i++)
                #pragma unroll
                for (int j = 0; j < TN; j++)
                    acc[i][j] = fmaf(a[i], b[j], acc[i][j]);
        }
        __syncthreads();
    }

    #pragma unroll
    for (int i = 0; i < TM; i++) {
        const long long crow = (long long)(m0 + tr * TM + i) * N;
        #pragma unroll
        for (int j = 0; j < TN; j++)
            Cb[crow + n0 + tc * TN + j] = acc[i][j];
    }
}

// ---------------------------------------------------------------------------
// Row softmax over rows of length SEQ (2048). One block (256 threads) per row.
// ---------------------------------------------------------------------------
__global__ __launch_bounds__(NTHREADS)
void softmax_rows(float* __restrict__ S)
{
    float* row = S + (long long)blockIdx.x * SEQ;
    const int tid = threadIdx.x;
    const int PER = SEQ / NTHREADS;  // 8

    float vals[PER];
    float mx = -INFINITY;
    #pragma unroll
    for (int i = 0; i < PER; i++) {
        vals[i] = row[tid + i * NTHREADS];
        mx = fmaxf(mx, vals[i]);
    }

    __shared__ float red[NTHREADS];
    red[tid] = mx;
    __syncthreads();
    for (int s = NTHREADS / 2; s > 0; s >>= 1) {
        if (tid < s) red[tid] = fmaxf(red[tid], red[tid + s]);
        __syncthreads();
    }
    mx = red[0];
    __syncthreads();

    float sum = 0.0f;
    #pragma unroll
    for (int i = 0; i < PER; i++) {
        vals[i] = expf(vals[i] - mx);
        sum += vals[i];
    }
    red[tid] = sum;
    __syncthreads();
    for (int s = NTHREADS / 2; s > 0; s >>= 1) {
        if (tid < s) red[tid] += red[tid + s];
        __syncthreads();
    }
    const float inv = 1.0f / red[0];

    #pragma unroll
    for (int i = 0; i < PER; i++)
        row[tid + i * NTHREADS] = vals[i] * inv;
}

// ---------------------------------------------------------------------------
// Launch
// ---------------------------------------------------------------------------
extern "C" void kernel_launch(void* const* d_in, const int* in_sizes, int n_in,
                              void* d_out, int out_size)
{
    const float* X  = (const float*)d_in[0];
    const float* Wq = (const float*)d_in[1];
    const float* bq = (const float*)d_in[2];
    const float* Wk = (const float*)d_in[3];
    const float* bk = (const float*)d_in[4];
    const float* Wv = (const float*)d_in[5];
    const float* bv = (const float*)d_in[6];
    float* out = (float*)d_out;

    float* q; cudaGetSymbolAddress((void**)&q, g_q);
    float* k; cudaGetSymbolAddress((void**)&k, g_k);
    float* v; cudaGetSymbolAddress((void**)&v, g_v);
    float* s; cudaGetSymbolAddress((void**)&s, g_s);

    const int M = BATCH * SEQ;  // 8192 rows for QKV projection

    // 1) QKV projections: [8192,1024] = X @ W^T + b
    {
        dim3 grid(HID / BN, M / BM, 1);
        gemm_nt<<<grid, NTHREADS>>>(X, Wq, bq, q, M, HID, HID, 1.0f, 0, 0, 0);
        gemm_nt<<<grid, NTHREADS>>>(X, Wk, bk, k, M, HID, HID, 1.0f, 0, 0, 0);
        gemm_nt<<<grid, NTHREADS>>>(X, Wv, bv, v, M, HID, HID, 1.0f, 0, 0, 0);
    }

    // 2) scores[b] = (q[b] @ k[b]^T) / 32
    {
        dim3 grid(SEQ / BN, SEQ / BM, BATCH);
        gemm_nt<<<grid, NTHREADS>>>(q, k, nullptr, s,
                                    SEQ, SEQ, HID, 1.0f / 32.0f,
                                    (long long)SEQ * HID, (long long)SEQ * HID,
                                    (long long)SEQ * SEQ);
    }

    // 3) row softmax over all B*S rows
    softmax_rows<<<BATCH * SEQ, NTHREADS>>>(s);

    // 4) out[b] = attn[b] @ v[b]
    {
        dim3 grid(HID / BN, SEQ / BM, BATCH);
        gemm_nn<<<grid, NTHREADS>>>(s, v, out,
                                    SEQ, HID, SEQ,
                                    (long long)SEQ * SEQ, (long long)SEQ * HID,
                                    (long long)SEQ * HID);
    }
}

// round 7
// speedup vs baseline: 3.8405x; 3.8405x over previous
#include <cuda_runtime.h>
#include <math.h>
#include <cstdint>

#define BATCH 4
#define SEQ   2048
#define HID   1024

// ---------------- scratch (allocation-free rule: __device__ globals) -------
__device__ float g_q [(size_t)BATCH * SEQ * HID];
__device__ float g_k [(size_t)BATCH * SEQ * HID];
__device__ float g_vT[(size_t)BATCH * SEQ * HID];   // [b][h][s]  (transposed V)
__device__ float g_s [(size_t)BATCH * SEQ * SEQ];

// ---------------- small ptx helpers ----------------------------------------
__device__ __forceinline__ uint32_t smem_u32(const void* p) {
    uint32_t a;
    asm("{ .reg .u64 t; cvta.to.shared.u64 t, %1; cvt.u32.u64 %0, t; }"
        : "=r"(a) : "l"(p));
    return a;
}
__device__ __forceinline__ void cp_async16(uint32_t saddr, const void* gaddr) {
    asm volatile("cp.async.cg.shared.global [%0], [%1], 16;"
                 :: "r"(saddr), "l"(gaddr) : "memory");
}
__device__ __forceinline__ void cp_commit() {
    asm volatile("cp.async.commit_group;" ::: "memory");
}
template<int N>
__device__ __forceinline__ void cp_wait() {
    asm volatile("cp.async.wait_group %0;" :: "n"(N) : "memory");
}
__device__ __forceinline__ uint32_t to_tf32(uint32_t bits) {
    uint32_t r;
    asm("cvt.rna.tf32.f32 %0, %1;" : "=r"(r) : "f"(__uint_as_float(bits)));
    return r;
}

// ---------------- tf32 mma.sync NT GEMM -------------------------------------
// C[m,n] = alpha * sum_k A[m,k]*B[n,k] (+bias[n])
// A:[M,K] ld=lda, B:[N,K] ld=ldb, 128x128 CTA tiles, K % 32 == 0.
// mode 0: C[z*sC + m*ldc + n]
// mode 1: transposed store C[(m>>11)*SEQ*HID + n*SEQ + (m&2047)]  (V^T)
#define BM 128
#define BN 128
#define BKF 32                      // K floats per chunk (128 B rows)
#define STAGES 3
#define TILE_B (BM * BKF * 4)       // 16 KB
#define STAGE_B (2 * TILE_B)        // A + B
#define SMEM_B (STAGES * STAGE_B)   // 96 KB

extern __shared__ char dyn_smem[];

__global__ void __launch_bounds__(256, 1)
gemm_tc(const float* __restrict__ A, const float* __restrict__ B,
        const float* __restrict__ bias, float* __restrict__ C,
        int K, int lda, int ldb, int ldc, float alpha,
        long long sA, long long sB, long long sC, int mode)
{
    const uint32_t smem_base = smem_u32(dyn_smem);
    const int tid  = threadIdx.x;
    const int wid  = tid >> 5;
    const int lane = tid & 31;
    const int wm   = wid >> 2;      // 0..1 : warp row  (64 rows each)
    const int wn   = wid & 3;       // 0..3 : warp col  (32 cols each)

    const int m0 = blockIdx.y * BM;
    const int n0 = blockIdx.x * BN;
    const long long z = blockIdx.z;

    const float* Ab = A + z * sA;
    const float* Bb = B + z * sB;

    // ---- global -> smem tile loader (swizzled: 16B chunk ch -> ch ^ (row&7))
    auto load_stage = [&](int chunk, int st) {
        const int k0 = chunk * BKF;
        const uint32_t sa = smem_base + st * STAGE_B;
        const uint32_t sb = sa + TILE_B;
        #pragma unroll
        for (int j = 0; j < 4; j++) {
            const int cid = tid + j * 256;          // 0..1023
            const int r   = cid >> 3;
            const int ch  = cid & 7;
            const uint32_t so = (uint32_t)r * 128 + (uint32_t)((ch ^ (r & 7)) << 4);
            cp_async16(sa + so, Ab + (long long)(m0 + r) * lda + k0 + ch * 4);
            cp_async16(sb + so, Bb + (long long)(n0 + r) * ldb + k0 + ch * 4);
        }
        cp_commit();
    };

    float acc[4][4][4];
    #pragma unroll
    for (int i = 0; i < 4; i++)
        #pragma unroll
        for (int j = 0; j < 4; j++)
            #pragma unroll
            for (int e = 0; e < 4; e++) acc[i][j][e] = 0.0f;

    const int NC = K / BKF;

    load_stage(0, 0);
    load_stage(1, 1);

    // ldmatrix per-lane addressing pieces
    const int a_r  = lane & 15;          // row within 16-row m-tile
    const int a_c  = lane >> 4;          // 0/1 -> 16B chunk offset within k-step
    const int b_r  = lane & 7;           // row within 8-row n-tile
    const int b_c  = (lane >> 3) & 1;

    for (int i = 0; i < NC; i++) {
        cp_wait<STAGES - 2>();
        __syncthreads();

        const uint32_t sa = smem_base + (i % STAGES) * STAGE_B;
        const uint32_t sb = sa + TILE_B;

        #pragma unroll
        for (int kk = 0; kk < 4; kk++) {            // 4 k-steps of 8
            uint32_t af[4][4], bf[4][2];
            #pragma unroll
            for (int mt = 0; mt < 4; mt++) {
                const int r  = wm * 64 + mt * 16 + a_r;
                const int ch = kk * 2 + a_c;
                const uint32_t ad = sa + (uint32_t)r * 128
                                       + (uint32_t)((ch ^ (r & 7)) << 4);
                asm volatile(
                    "ldmatrix.sync.aligned.m8n8.x4.shared.b16 {%0,%1,%2,%3}, [%4];"
                    : "=r"(af[mt][0]), "=r"(af[mt][1]),
                      "=r"(af[mt][2]), "=r"(af[mt][3]) : "r"(ad));
            }
            #pragma unroll
            for (int nt = 0; nt < 4; nt++) {
                const int r  = wn * 32 + nt * 8 + b_r;
                const int ch = kk * 2 + b_c;
                const uint32_t bd = sb + (uint32_t)r * 128
                                       + (uint32_t)((ch ^ (r & 7)) << 4);
                asm volatile(
                    "ldmatrix.sync.aligned.m8n8.x2.shared.b16 {%0,%1}, [%2];"
                    : "=r"(bf[nt][0]), "=r"(bf[nt][1]) : "r"(bd));
            }
            // round-to-nearest tf32 conversion (truncation would bias K-long dots)
            #pragma unroll
            for (int mt = 0; mt < 4; mt++)
                #pragma unroll
                for (int e = 0; e < 4; e++) af[mt][e] = to_tf32(af[mt][e]);
            #pragma unroll
            for (int nt = 0; nt < 4; nt++) {
                bf[nt][0] = to_tf32(bf[nt][0]);
                bf[nt][1] = to_tf32(bf[nt][1]);
            }
            #pragma unroll
            for (int mt = 0; mt < 4; mt++)
                #pragma unroll
                for (int nt = 0; nt < 4; nt++) {
                    asm volatile(
                        "mma.sync.aligned.m16n8k8.row.col.f32.tf32.tf32.f32 "
                        "{%0,%1,%2,%3}, {%4,%5,%6,%7}, {%8,%9}, {%0,%1,%2,%3};"
                        : "+f"(acc[mt][nt][0]), "+f"(acc[mt][nt][1]),
                          "+f"(acc[mt][nt][2]), "+f"(acc[mt][nt][3])
                        : "r"(af[mt][0]), "r"(af[mt][1]),
                          "r"(af[mt][2]), "r"(af[mt][3]),
                          "r"(bf[nt][0]), "r"(bf[nt][1]));
                }
        }

        if (i + 2 < NC) load_stage(i + 2, (i + 2) % STAGES);
        else            cp_commit();     // keep group accounting consistent
    }

    // ---- epilogue (fragment layout: c0,c1 = row g cols 2c,2c+1; c2,c3 = row g+8)
    const int g  = lane >> 2;
    const int cc = (lane & 3) * 2;

    #pragma unroll
    for (int mt = 0; mt < 4; mt++) {
        #pragma unroll
        for (int nt = 0; nt < 4; nt++) {
            const int row0 = m0 + wm * 64 + mt * 16 + g;
            const int col  = n0 + wn * 32 + nt * 8 + cc;
            #pragma unroll
            for (int h = 0; h < 2; h++) {           // h=0: row g, h=1: row g+8
                const int row = row0 + h * 8;
                float v0 = alpha * acc[mt][nt][h * 2 + 0];
                float v1 = alpha * acc[mt][nt][h * 2 + 1];
                if (bias) {
                    v0 += __ldg(&bias[col + 0]);
                    v1 += __ldg(&bias[col + 1]);
                }
                if (mode == 0) {
                    float2* dst = reinterpret_cast<float2*>(
                        C + z * sC + (long long)row * ldc + col);
                    *dst = make_float2(v0, v1);
                } else {
                    const long long b_idx = row >> 11;
                    const long long s_loc = row & (SEQ - 1);
                    C[b_idx * SEQ * HID + (long long)(col + 0) * SEQ + s_loc] = v0;
                    C[b_idx * SEQ * HID + (long long)(col + 1) * SEQ + s_loc] = v1;
                }
            }
        }
    }
}

// ---------------- softmax ---------------------------------------------------
#define SOFT_THREADS 256
__global__ void __launch_bounds__(SOFT_THREADS)
softmax_rows(float* __restrict__ S)
{
    float* row = S + (long long)blockIdx.x * SEQ;
    const int tid = threadIdx.x;
    const int PER = SEQ / SOFT_THREADS;  // 8

    float vals[PER];
    float mx = -INFINITY;
    #pragma unroll
    for (int i = 0; i < PER; i++) {
        vals[i] = row[tid + i * SOFT_THREADS];
        mx = fmaxf(mx, vals[i]);
    }

    __shared__ float red[SOFT_THREADS];
    red[tid] = mx;
    __syncthreads();
    for (int s = SOFT_THREADS / 2; s > 0; s >>= 1) {
        if (tid < s) red[tid] = fmaxf(red[tid], red[tid + s]);
        __syncthreads();
    }
    mx = red[0];
    __syncthreads();

    float sum = 0.0f;
    #pragma unroll
    for (int i = 0; i < PER; i++) {
        vals[i] = expf(vals[i] - mx);
        sum += vals[i];
    }
    red[tid] = sum;
    __syncthreads();
    for (int s = SOFT_THREADS / 2; s > 0; s >>= 1) {
        if (tid < s) red[tid] += red[tid + s];
        __syncthreads();
    }
    const float inv = 1.0f / red[0];

    #pragma unroll
    for (int i = 0; i < PER; i++)
        row[tid + i * SOFT_THREADS] = vals[i] * inv;
}

// ---------------- launch ----------------------------------------------------
extern "C" void kernel_launch(void* const* d_in, const int* in_sizes, int n_in,
                              void* d_out, int out_size)
{
    const float* X  = (const float*)d_in[0];
    const float* Wq = (const float*)d_in[1];
    const float* bq = (const float*)d_in[2];
    const float* Wk = (const float*)d_in[3];
    const float* bk = (const float*)d_in[4];
    const float* Wv = (const float*)d_in[5];
    const float* bv = (const float*)d_in[6];
    float* out = (float*)d_out;

    float* q;  cudaGetSymbolAddress((void**)&q,  g_q);
    float* k;  cudaGetSymbolAddress((void**)&k,  g_k);
    float* vT; cudaGetSymbolAddress((void**)&vT, g_vT);
    float* s;  cudaGetSymbolAddress((void**)&s,  g_s);

    cudaFuncSetAttribute(gemm_tc, cudaFuncAttributeMaxDynamicSharedMemorySize,
                         SMEM_B);

    const int M = BATCH * SEQ;  // 8192

    // 1) Q,K projections + V projection stored transposed
    {
        dim3 grid(HID / BN, M / BM, 1);
        gemm_tc<<<grid, 256, SMEM_B>>>(X, Wq, bq, q,  HID, HID, HID, HID,
                                       1.0f, 0, 0, 0, 0);
        gemm_tc<<<grid, 256, SMEM_B>>>(X, Wk, bk, k,  HID, HID, HID, HID,
                                       1.0f, 0, 0, 0, 0);
        gemm_tc<<<grid, 256, SMEM_B>>>(X, Wv, bv, vT, HID, HID, HID, 0,
                                       1.0f, 0, 0, 0, 1);
    }

    // 2) scores[b] = (q[b] @ k[b]^T) / 32
    {
        dim3 grid(SEQ / BN, SEQ / BM, BATCH);
        gemm_tc<<<grid, 256, SMEM_B>>>(q, k, nullptr, s,
                                       HID, HID, HID, SEQ, 1.0f / 32.0f,
                                       (long long)SEQ * HID,
                                       (long long)SEQ * HID,
                                       (long long)SEQ * SEQ, 0);
    }

    // 3) softmax over all B*S rows
    softmax_rows<<<BATCH * SEQ, SOFT_THREADS>>>(s);

    // 4) out[b] = attn[b] @ v[b] = NT(attn, vT)
    {
        dim3 grid(HID / BN, SEQ / BM, BATCH);
        gemm_tc<<<grid, 256, SMEM_B>>>(s, vT, nullptr, out,
                                       SEQ, SEQ, SEQ, HID, 1.0f,
                                       (long long)SEQ * SEQ,
                                       (long long)SEQ * HID,
                                       (long long)SEQ * HID, 0);
    }
}